// round 3
// baseline (speedup 1.0000x reference)
#include <cuda_runtime.h>
#include <cfloat>

#define NN 50000
#define NE 600000
#define D  128
#define NB 8

// ---------------- scratch (static device memory; no allocs) ----------------
__device__ float g_z [NN * D];   // (1+eps)*x + scatter-add  (GEMM1 input)
__device__ float g_u [NN * D];   // GEMM1 output (pre-BN)
__device__ float g_v [NN * D];   // GEMM2 output (pre-BN)
__device__ float g_h1[NN * D];   // layer-0 output
__device__ float g_sum[4 * D];   // column sums   [layer*2 + stage]
__device__ float g_ss [4 * D];   // column sumsq
__device__ float g_pool[3 * NB * D]; // segment-max of h, h1, h2

__device__ __forceinline__ void atomicMaxFloat(float* addr, float v) {
    if (v >= 0.f) atomicMax((int*)addr, __float_as_int(v));
    else          atomicMin((unsigned int*)addr, __float_as_uint(v));
}

// ---------------- init: zero stats, pool = -FLT_MAX ----------------
__global__ void k_init() {
    int t = threadIdx.x;
    if (t < 4 * D) { g_sum[t] = 0.f; g_ss[t] = 0.f; }
    for (int i = t; i < 3 * NB * D; i += 1024) g_pool[i] = -FLT_MAX;
}

// ---------------- z = (1+eps) * x ----------------
__global__ __launch_bounds__(256) void k_initz(const float* __restrict__ x,
                                               const float* __restrict__ epsp) {
    float s = 1.0f + *epsp;
    size_t i = ((size_t)blockIdx.x * 256 + threadIdx.x) * 4;
    float4 v = *(const float4*)(x + i);
    v.x *= s; v.y *= s; v.z *= s; v.w *= s;
    *(float4*)(g_z + i) = v;
}

// ---------------- scatter: z[dst] += x[src], warp per edge ----------------
__global__ __launch_bounds__(256) void k_scatter(const float* __restrict__ x,
                                                 const int* __restrict__ src,
                                                 const int* __restrict__ dst) {
    int idx  = blockIdx.x * 256 + threadIdx.x;
    int e    = idx >> 5;
    int lane = idx & 31;
    if (e >= NE) return;
    int s = src[e], d = dst[e];
    float4 val = *(const float4*)(x + (size_t)s * D + lane * 4);
    float* base = g_z + (size_t)d * D + lane * 4;
    atomicAdd(base + 0, val.x);
    atomicAdd(base + 1, val.y);
    atomicAdd(base + 2, val.z);
    atomicAdd(base + 3, val.w);
}

// ---------------- GEMM (64 rows x 128 cols per block, K=128) ---------------
// bnrelu=0: out = A @ W + bias                 (+ column stats)
// bnrelu=1: out = relu(bn(A)) @ W + bias       (+ column stats)
__global__ __launch_bounds__(256) void k_gemm(
    const float* __restrict__ A, const float* __restrict__ W,
    const float* __restrict__ bias, float* __restrict__ out,
    const float* __restrict__ in_sum, const float* __restrict__ in_ss,
    const float* __restrict__ gamma, const float* __restrict__ beta,
    float* __restrict__ out_sum, float* __restrict__ out_ss,
    int bnrelu)
{
    __shared__ float zs[16][64];
    __shared__ float ws[16][128];
    __shared__ float sc_s[128];
    __shared__ float sh_s[128];
    const int tid = threadIdx.x;

    if (bnrelu) {
        if (tid < 128) {
            float m   = in_sum[tid] * (1.0f / NN);
            float var = in_ss[tid] * (1.0f / NN) - m * m;
            float rs  = rsqrtf(var + 1e-5f);
            float sc  = gamma[tid] * rs;
            sc_s[tid] = sc;
            sh_s[tid] = fmaf(-m, sc, beta[tid]);
        }
        __syncthreads();
    }

    const int row0  = blockIdx.x * 64;
    const int row_t = tid >> 5;       // 0..7
    const int col_t = tid & 31;       // 0..31
    float acc[8][4];
#pragma unroll
    for (int i = 0; i < 8; i++)
#pragma unroll
        for (int j = 0; j < 4; j++) acc[i][j] = 0.f;

    const int lr = tid >> 2;          // loader row 0..63
    const int lk = (tid & 3) * 4;     // loader k-offset
    const int g_lr = row0 + lr;

    for (int kk = 0; kk < D; kk += 16) {
        float4 v = make_float4(0.f, 0.f, 0.f, 0.f);
        if (g_lr < NN) v = *(const float4*)(A + (size_t)g_lr * D + kk + lk);
        if (bnrelu) {
            int kb = kk + lk;
            v.x = fmaxf(fmaf(v.x, sc_s[kb + 0], sh_s[kb + 0]), 0.f);
            v.y = fmaxf(fmaf(v.y, sc_s[kb + 1], sh_s[kb + 1]), 0.f);
            v.z = fmaxf(fmaf(v.z, sc_s[kb + 2], sh_s[kb + 2]), 0.f);
            v.w = fmaxf(fmaf(v.w, sc_s[kb + 3], sh_s[kb + 3]), 0.f);
        }
        zs[lk + 0][lr] = v.x; zs[lk + 1][lr] = v.y;
        zs[lk + 2][lr] = v.z; zs[lk + 3][lr] = v.w;
#pragma unroll
        for (int i = 0; i < 2; i++) {
            int f = tid + i * 256;
            int k = f >> 5, c4 = (f & 31) * 4;
            *(float4*)&ws[k][c4] = *(const float4*)(W + (size_t)(kk + k) * D + c4);
        }
        __syncthreads();
#pragma unroll
        for (int k = 0; k < 16; k++) {
            float4 w4 = *(float4*)&ws[k][col_t * 4];
            float4 z0 = *(float4*)&zs[k][row_t * 8];
            float4 z1 = *(float4*)&zs[k][row_t * 8 + 4];
            float zr[8] = {z0.x, z0.y, z0.z, z0.w, z1.x, z1.y, z1.z, z1.w};
#pragma unroll
            for (int i = 0; i < 8; i++) {
                acc[i][0] = fmaf(zr[i], w4.x, acc[i][0]);
                acc[i][1] = fmaf(zr[i], w4.y, acc[i][1]);
                acc[i][2] = fmaf(zr[i], w4.z, acc[i][2]);
                acc[i][3] = fmaf(zr[i], w4.w, acc[i][3]);
            }
        }
        __syncthreads();
    }

    const int c0 = col_t * 4;
    float4 b4 = *(const float4*)(bias + c0);
    float bb[4] = {b4.x, b4.y, b4.z, b4.w};
    float psum[4] = {0, 0, 0, 0}, pss[4] = {0, 0, 0, 0};
#pragma unroll
    for (int i = 0; i < 8; i++) {
        int gr = row0 + row_t * 8 + i;
        if (gr < NN) {
            float vals[4];
#pragma unroll
            for (int j = 0; j < 4; j++) {
                float val = acc[i][j] + bb[j];
                vals[j] = val;
                psum[j] += val;
                pss[j]  += val * val;
            }
            float4 o; o.x = vals[0]; o.y = vals[1]; o.z = vals[2]; o.w = vals[3];
            *(float4*)(out + (size_t)gr * D + c0) = o;
        }
    }
    __syncthreads();
    float* sumbuf = &ws[0][0];  // 8*128 floats
    float* ssbuf  = &zs[0][0];  // 8*128 floats (16*64 = 1024)
#pragma unroll
    for (int j = 0; j < 4; j++) {
        sumbuf[row_t * 128 + c0 + j] = psum[j];
        ssbuf [row_t * 128 + c0 + j] = pss[j];
    }
    __syncthreads();
    if (row_t == 0) {
#pragma unroll
        for (int j = 0; j < 4; j++) {
            int c = c0 + j;
            float s = 0.f, q = 0.f;
#pragma unroll
            for (int p = 0; p < 8; p++) { s += sumbuf[p * 128 + c]; q += ssbuf[p * 128 + c]; }
            atomicAdd(&out_sum[c], s);
            atomicAdd(&out_ss[c], q);
        }
    }
}

// -------- y = leaky_relu(bn(v)); write y; segment-max pooling --------------
__global__ __launch_bounds__(256) void k_out(
    const float* __restrict__ v, const float* __restrict__ in_sum,
    const float* __restrict__ in_ss, const float* __restrict__ gamma,
    const float* __restrict__ beta, float* __restrict__ y,
    float* __restrict__ pool, const int* __restrict__ seg)
{
    __shared__ float sc_s[128], sh_s[128];
    __shared__ int seg_s[128];
    int tid  = threadIdx.x;
    int row0 = blockIdx.x * 128;
    if (tid < 128) {
        float m   = in_sum[tid] * (1.0f / NN);
        float var = in_ss[tid] * (1.0f / NN) - m * m;
        float rs  = rsqrtf(var + 1e-5f);
        float sc  = gamma[tid] * rs;
        sc_s[tid] = sc;
        sh_s[tid] = fmaf(-m, sc, beta[tid]);
        int r = row0 + tid;
        seg_s[tid] = (r < NN) ? seg[r] : -1;
    }
    __syncthreads();
    int c    = tid & 127;
    int rbeg = (tid >> 7) * 64;
    float sc = sc_s[c], sh = sh_s[c];
    float runmax = -FLT_MAX;
    int cur = -1;
    for (int i = 0; i < 64; i++) {
        int r = rbeg + i, gr = row0 + r;
        if (gr >= NN) break;
        float val = fmaf(v[(size_t)gr * D + c], sc, sh);
        val = (val > 0.f) ? val : val * 0.01f;
        y[(size_t)gr * D + c] = val;
        int s = seg_s[r];
        if (s != cur) {
            if (cur >= 0) atomicMaxFloat(&pool[cur * D + c], runmax);
            cur = s; runmax = val;
        } else runmax = fmaxf(runmax, val);
    }
    if (cur >= 0) atomicMaxFloat(&pool[cur * D + c], runmax);
}

// -------- segment-max pooling of raw input h --------------
__global__ __launch_bounds__(256) void k_pool0(const float* __restrict__ x,
                                               const int* __restrict__ seg,
                                               float* __restrict__ pool)
{
    __shared__ int seg_s[128];
    int tid  = threadIdx.x;
    int row0 = blockIdx.x * 128;
    if (tid < 128) { int r = row0 + tid; seg_s[tid] = (r < NN) ? seg[r] : -1; }
    __syncthreads();
    int c    = tid & 127;
    int rbeg = (tid >> 7) * 64;
    float runmax = -FLT_MAX;
    int cur = -1;
    for (int i = 0; i < 64; i++) {
        int r = rbeg + i, gr = row0 + r;
        if (gr >= NN) break;
        float val = x[(size_t)gr * D + c];
        int s = seg_s[r];
        if (s != cur) {
            if (cur >= 0) atomicMaxFloat(&pool[cur * D + c], runmax);
            cur = s; runmax = val;
        } else runmax = fmaxf(runmax, val);
    }
    if (cur >= 0) atomicMaxFloat(&pool[cur * D + c], runmax);
}

// -------- score = sum_l pooled_l @ pW_l + pb_l  (8x128, one block) ---------
__global__ __launch_bounds__(256) void k_score(
    const float* __restrict__ W0, const float* __restrict__ b0,
    const float* __restrict__ W1, const float* __restrict__ b1,
    const float* __restrict__ W2, const float* __restrict__ b2,
    float* __restrict__ out)
{
    __shared__ float ps[3 * NB * D];
    int tid = threadIdx.x;
    for (int i = tid; i < 3 * NB * D; i += 256) ps[i] = g_pool[i];
    __syncthreads();
    int b  = tid >> 5;          // 0..7
    int j0 = (tid & 31) * 4;    // 0..124
    float acc[4];
#pragma unroll
    for (int j = 0; j < 4; j++) acc[j] = b0[j0 + j] + b1[j0 + j] + b2[j0 + j];
    const float* Ws[3] = {W0, W1, W2};
    for (int l = 0; l < 3; l++) {
        const float* pl = ps + (l * NB + b) * D;
        const float* Wl = Ws[l];
        for (int k = 0; k < D; k++) {
            float p = pl[k];
            float4 w = *(const float4*)(Wl + (size_t)k * D + j0);
            acc[0] = fmaf(p, w.x, acc[0]);
            acc[1] = fmaf(p, w.y, acc[1]);
            acc[2] = fmaf(p, w.z, acc[2]);
            acc[3] = fmaf(p, w.w, acc[3]);
        }
    }
#pragma unroll
    for (int j = 0; j < 4; j++) out[b * D + j0 + j] = acc[j];
}

// ---------------------------------------------------------------------------
extern "C" void kernel_launch(void* const* d_in, const int* in_sizes, int n_in,
                              void* d_out, int out_size)
{
    const float* h   = (const float*)d_in[0];
    const int*   src = (const int*)d_in[1];
    const int*   dst = (const int*)d_in[2];
    const int*   seg = (const int*)d_in[3];
    const float* c_eps[2] = {(const float*)d_in[4],  (const float*)d_in[13]};
    const float* c_W1 [2] = {(const float*)d_in[5],  (const float*)d_in[14]};
    const float* c_b1 [2] = {(const float*)d_in[6],  (const float*)d_in[15]};
    const float* c_g1 [2] = {(const float*)d_in[7],  (const float*)d_in[16]};
    const float* c_be1[2] = {(const float*)d_in[8],  (const float*)d_in[17]};
    const float* c_W2 [2] = {(const float*)d_in[9],  (const float*)d_in[18]};
    const float* c_b2 [2] = {(const float*)d_in[10], (const float*)d_in[19]};
    const float* c_g2 [2] = {(const float*)d_in[11], (const float*)d_in[20]};
    const float* c_be2[2] = {(const float*)d_in[12], (const float*)d_in[21]};
    const float* pW[3] = {(const float*)d_in[22], (const float*)d_in[24], (const float*)d_in[26]};
    const float* pb[3] = {(const float*)d_in[23], (const float*)d_in[25], (const float*)d_in[27]};

    float* out_h2 = (float*)d_out;
    float* out_sc = (float*)d_out + (size_t)NN * D;

    float *z, *u, *v, *h1, *sums, *sss, *pool;
    cudaGetSymbolAddress((void**)&z,    g_z);
    cudaGetSymbolAddress((void**)&u,    g_u);
    cudaGetSymbolAddress((void**)&v,    g_v);
    cudaGetSymbolAddress((void**)&h1,   g_h1);
    cudaGetSymbolAddress((void**)&sums, g_sum);
    cudaGetSymbolAddress((void**)&sss,  g_ss);
    cudaGetSymbolAddress((void**)&pool, g_pool);

    const int GEMM_BLOCKS = (NN + 63) / 64;     // 782
    const int ROW_BLOCKS  = (NN + 127) / 128;   // 391

    k_init<<<1, 1024>>>();
    k_pool0<<<ROW_BLOCKS, 256>>>(h, seg, pool);

    const float* x = h;
    float* youts[2] = {h1, out_h2};
    for (int l = 0; l < 2; l++) {
        k_initz  <<<(NN * D) / 1024, 256>>>(x, c_eps[l]);
        k_scatter<<<(NE * 32) / 256, 256>>>(x, src, dst);
        float* s1 = sums + (l * 2 + 0) * D; float* q1 = sss + (l * 2 + 0) * D;
        float* s2 = sums + (l * 2 + 1) * D; float* q2 = sss + (l * 2 + 1) * D;
        k_gemm<<<GEMM_BLOCKS, 256>>>(z, c_W1[l], c_b1[l], u,
                                     nullptr, nullptr, nullptr, nullptr,
                                     s1, q1, 0);
        k_gemm<<<GEMM_BLOCKS, 256>>>(u, c_W2[l], c_b2[l], v,
                                     s1, q1, c_g1[l], c_be1[l],
                                     s2, q2, 1);
        k_out<<<ROW_BLOCKS, 256>>>(v, s2, q2, c_g2[l], c_be2[l],
                                   youts[l], pool + (size_t)(l + 1) * NB * D, seg);
        x = h1;
    }
    k_score<<<1, 256>>>(pW[0], pb[0], pW[1], pb[1], pW[2], pb[2], out_sc);
}

// round 4
// speedup vs baseline: 1.4776x; 1.4776x over previous
#include <cuda_runtime.h>
#include <cfloat>

#define NN 50000
#define NE 600000
#define D  128
#define NB 8

// ---------------- scratch (static device memory; no allocs) ----------------
__device__ float g_z [NN * D];   // (1+eps)*x + scatter-add  (GEMM1 input)
__device__ float g_u [NN * D];   // GEMM1 output (pre-BN)
__device__ float g_v [NN * D];   // GEMM2 output (pre-BN)
__device__ float g_h1[NN * D];   // layer-0 output
__device__ float g_sum[4 * D];   // column sums   [layer*2 + stage]
__device__ float g_ss [4 * D];   // column sumsq
__device__ float g_pool[3 * NB * D]; // segment-max of h, h1, h2

__device__ __forceinline__ void atomicMaxFloat(float* addr, float v) {
    if (v >= 0.f) atomicMax((int*)addr, __float_as_int(v));
    else          atomicMin((unsigned int*)addr, __float_as_uint(v));
}

// ---------------- init: zero stats, pool = -FLT_MAX ----------------
__global__ void k_init() {
    int t = threadIdx.x;
    if (t < 4 * D) { g_sum[t] = 0.f; g_ss[t] = 0.f; }
    for (int i = t; i < 3 * NB * D; i += 1024) g_pool[i] = -FLT_MAX;
}

// ---------------- z = (1+eps) * x ----------------
__global__ __launch_bounds__(256) void k_initz(const float* __restrict__ x,
                                               const float* __restrict__ epsp) {
    float s = 1.0f + *epsp;
    size_t i = ((size_t)blockIdx.x * 256 + threadIdx.x) * 4;
    float4 v = *(const float4*)(x + i);
    v.x *= s; v.y *= s; v.z *= s; v.w *= s;
    *(float4*)(g_z + i) = v;
}

// ------- scatter: z[dst] += x[src]; warp per 4 edges, red.global.v4 --------
#define EPW 4   // edges per warp
__global__ __launch_bounds__(256) void k_scatter(const float* __restrict__ x,
                                                 const int* __restrict__ src,
                                                 const int* __restrict__ dst) {
    int warp = (blockIdx.x * 256 + threadIdx.x) >> 5;
    int lane = threadIdx.x & 31;
    int e0   = warp * EPW;                      // NE divisible by EPW
    int4 s4 = *(const int4*)(src + e0);
    int4 d4 = *(const int4*)(dst + e0);
    int ss[EPW] = {s4.x, s4.y, s4.z, s4.w};
    int dd[EPW] = {d4.x, d4.y, d4.z, d4.w};
    float4 v[EPW];
#pragma unroll
    for (int i = 0; i < EPW; i++)
        v[i] = *(const float4*)(x + (size_t)ss[i] * D + lane * 4);
#pragma unroll
    for (int i = 0; i < EPW; i++) {
        float* p = g_z + (size_t)dd[i] * D + lane * 4;
        asm volatile("red.global.add.v4.f32 [%0], {%1, %2, %3, %4};"
                     :: "l"(p), "f"(v[i].x), "f"(v[i].y), "f"(v[i].z), "f"(v[i].w)
                     : "memory");
    }
}

// ---------------- GEMM (64 rows x 128 cols per block, K=128) ---------------
// bnrelu=0: out = A @ W + bias                 (+ column stats)
// bnrelu=1: out = relu(bn(A)) @ W + bias       (+ column stats)
__global__ __launch_bounds__(256) void k_gemm(
    const float* __restrict__ A, const float* __restrict__ W,
    const float* __restrict__ bias, float* __restrict__ out,
    const float* __restrict__ in_sum, const float* __restrict__ in_ss,
    const float* __restrict__ gamma, const float* __restrict__ beta,
    float* __restrict__ out_sum, float* __restrict__ out_ss,
    int bnrelu)
{
    __shared__ float zs[16][64];
    __shared__ float ws[16][128];
    __shared__ float sc_s[128];
    __shared__ float sh_s[128];
    const int tid = threadIdx.x;

    if (bnrelu) {
        if (tid < 128) {
            float m   = in_sum[tid] * (1.0f / NN);
            float var = in_ss[tid] * (1.0f / NN) - m * m;
            float rs  = rsqrtf(var + 1e-5f);
            float sc  = gamma[tid] * rs;
            sc_s[tid] = sc;
            sh_s[tid] = fmaf(-m, sc, beta[tid]);
        }
        __syncthreads();
    }

    const int row0  = blockIdx.x * 64;
    const int row_t = tid >> 5;       // 0..7
    const int col_t = tid & 31;       // 0..31
    float acc[8][4];
#pragma unroll
    for (int i = 0; i < 8; i++)
#pragma unroll
        for (int j = 0; j < 4; j++) acc[i][j] = 0.f;

    const int lr = tid >> 2;          // loader row 0..63
    const int lk = (tid & 3) * 4;     // loader k-offset
    const int g_lr = row0 + lr;

    for (int kk = 0; kk < D; kk += 16) {
        float4 v = make_float4(0.f, 0.f, 0.f, 0.f);
        if (g_lr < NN) v = *(const float4*)(A + (size_t)g_lr * D + kk + lk);
        if (bnrelu) {
            int kb = kk + lk;
            v.x = fmaxf(fmaf(v.x, sc_s[kb + 0], sh_s[kb + 0]), 0.f);
            v.y = fmaxf(fmaf(v.y, sc_s[kb + 1], sh_s[kb + 1]), 0.f);
            v.z = fmaxf(fmaf(v.z, sc_s[kb + 2], sh_s[kb + 2]), 0.f);
            v.w = fmaxf(fmaf(v.w, sc_s[kb + 3], sh_s[kb + 3]), 0.f);
        }
        zs[lk + 0][lr] = v.x; zs[lk + 1][lr] = v.y;
        zs[lk + 2][lr] = v.z; zs[lk + 3][lr] = v.w;
#pragma unroll
        for (int i = 0; i < 2; i++) {
            int f = tid + i * 256;
            int k = f >> 5, c4 = (f & 31) * 4;
            *(float4*)&ws[k][c4] = *(const float4*)(W + (size_t)(kk + k) * D + c4);
        }
        __syncthreads();
#pragma unroll
        for (int k = 0; k < 16; k++) {
            float4 w4 = *(float4*)&ws[k][col_t * 4];
            float4 z0 = *(float4*)&zs[k][row_t * 8];
            float4 z1 = *(float4*)&zs[k][row_t * 8 + 4];
            float zr[8] = {z0.x, z0.y, z0.z, z0.w, z1.x, z1.y, z1.z, z1.w};
#pragma unroll
            for (int i = 0; i < 8; i++) {
                acc[i][0] = fmaf(zr[i], w4.x, acc[i][0]);
                acc[i][1] = fmaf(zr[i], w4.y, acc[i][1]);
                acc[i][2] = fmaf(zr[i], w4.z, acc[i][2]);
                acc[i][3] = fmaf(zr[i], w4.w, acc[i][3]);
            }
        }
        __syncthreads();
    }

    const int c0 = col_t * 4;
    float4 b4 = *(const float4*)(bias + c0);
    float bb[4] = {b4.x, b4.y, b4.z, b4.w};
    float psum[4] = {0, 0, 0, 0}, pss[4] = {0, 0, 0, 0};
#pragma unroll
    for (int i = 0; i < 8; i++) {
        int gr = row0 + row_t * 8 + i;
        if (gr < NN) {
            float vals[4];
#pragma unroll
            for (int j = 0; j < 4; j++) {
                float val = acc[i][j] + bb[j];
                vals[j] = val;
                psum[j] += val;
                pss[j]  += val * val;
            }
            float4 o; o.x = vals[0]; o.y = vals[1]; o.z = vals[2]; o.w = vals[3];
            *(float4*)(out + (size_t)gr * D + c0) = o;
        }
    }
    __syncthreads();
    float* sumbuf = &ws[0][0];  // 8*128 floats
    float* ssbuf  = &zs[0][0];  // 8*128 floats (16*64 = 1024)
#pragma unroll
    for (int j = 0; j < 4; j++) {
        sumbuf[row_t * 128 + c0 + j] = psum[j];
        ssbuf [row_t * 128 + c0 + j] = pss[j];
    }
    __syncthreads();
    if (row_t == 0) {
#pragma unroll
        for (int j = 0; j < 4; j++) {
            int c = c0 + j;
            float s = 0.f, q = 0.f;
#pragma unroll
            for (int p = 0; p < 8; p++) { s += sumbuf[p * 128 + c]; q += ssbuf[p * 128 + c]; }
            atomicAdd(&out_sum[c], s);
            atomicAdd(&out_ss[c], q);
        }
    }
}

// -------- y = leaky_relu(bn(v)); write y; segment-max pooling --------------
__global__ __launch_bounds__(256) void k_out(
    const float* __restrict__ v, const float* __restrict__ in_sum,
    const float* __restrict__ in_ss, const float* __restrict__ gamma,
    const float* __restrict__ beta, float* __restrict__ y,
    float* __restrict__ pool, const int* __restrict__ seg)
{
    __shared__ float sc_s[128], sh_s[128];
    __shared__ int seg_s[128];
    int tid  = threadIdx.x;
    int row0 = blockIdx.x * 128;
    if (tid < 128) {
        float m   = in_sum[tid] * (1.0f / NN);
        float var = in_ss[tid] * (1.0f / NN) - m * m;
        float rs  = rsqrtf(var + 1e-5f);
        float sc  = gamma[tid] * rs;
        sc_s[tid] = sc;
        sh_s[tid] = fmaf(-m, sc, beta[tid]);
        int r = row0 + tid;
        seg_s[tid] = (r < NN) ? seg[r] : -1;
    }
    __syncthreads();
    int c    = tid & 127;
    int rbeg = (tid >> 7) * 64;
    float sc = sc_s[c], sh = sh_s[c];
    float runmax = -FLT_MAX;
    int cur = -1;
    for (int i = 0; i < 64; i++) {
        int r = rbeg + i, gr = row0 + r;
        if (gr >= NN) break;
        float val = fmaf(v[(size_t)gr * D + c], sc, sh);
        val = (val > 0.f) ? val : val * 0.01f;
        y[(size_t)gr * D + c] = val;
        int s = seg_s[r];
        if (s != cur) {
            if (cur >= 0) atomicMaxFloat(&pool[cur * D + c], runmax);
            cur = s; runmax = val;
        } else runmax = fmaxf(runmax, val);
    }
    if (cur >= 0) atomicMaxFloat(&pool[cur * D + c], runmax);
}

// -------- segment-max pooling of raw input h --------------
__global__ __launch_bounds__(256) void k_pool0(const float* __restrict__ x,
                                               const int* __restrict__ seg,
                                               float* __restrict__ pool)
{
    __shared__ int seg_s[128];
    int tid  = threadIdx.x;
    int row0 = blockIdx.x * 128;
    if (tid < 128) { int r = row0 + tid; seg_s[tid] = (r < NN) ? seg[r] : -1; }
    __syncthreads();
    int c    = tid & 127;
    int rbeg = (tid >> 7) * 64;
    float runmax = -FLT_MAX;
    int cur = -1;
    for (int i = 0; i < 64; i++) {
        int r = rbeg + i, gr = row0 + r;
        if (gr >= NN) break;
        float val = x[(size_t)gr * D + c];
        int s = seg_s[r];
        if (s != cur) {
            if (cur >= 0) atomicMaxFloat(&pool[cur * D + c], runmax);
            cur = s; runmax = val;
        } else runmax = fmaxf(runmax, val);
    }
    if (cur >= 0) atomicMaxFloat(&pool[cur * D + c], runmax);
}

// -------- score = sum_l pooled_l @ pW_l + pb_l  (8x128, one block) ---------
__global__ __launch_bounds__(256) void k_score(
    const float* __restrict__ W0, const float* __restrict__ b0,
    const float* __restrict__ W1, const float* __restrict__ b1,
    const float* __restrict__ W2, const float* __restrict__ b2,
    float* __restrict__ out)
{
    __shared__ float ps[3 * NB * D];
    int tid = threadIdx.x;
    for (int i = tid; i < 3 * NB * D; i += 256) ps[i] = g_pool[i];
    __syncthreads();
    int b  = tid >> 5;          // 0..7
    int j0 = (tid & 31) * 4;    // 0..124
    float acc[4];
#pragma unroll
    for (int j = 0; j < 4; j++) acc[j] = b0[j0 + j] + b1[j0 + j] + b2[j0 + j];
    const float* Ws[3] = {W0, W1, W2};
    for (int l = 0; l < 3; l++) {
        const float* pl = ps + (l * NB + b) * D;
        const float* Wl = Ws[l];
        for (int k = 0; k < D; k++) {
            float p = pl[k];
            float4 w = *(const float4*)(Wl + (size_t)k * D + j0);
            acc[0] = fmaf(p, w.x, acc[0]);
            acc[1] = fmaf(p, w.y, acc[1]);
            acc[2] = fmaf(p, w.z, acc[2]);
            acc[3] = fmaf(p, w.w, acc[3]);
        }
    }
#pragma unroll
    for (int j = 0; j < 4; j++) out[b * D + j0 + j] = acc[j];
}

// ---------------------------------------------------------------------------
extern "C" void kernel_launch(void* const* d_in, const int* in_sizes, int n_in,
                              void* d_out, int out_size)
{
    const float* h   = (const float*)d_in[0];
    const int*   src = (const int*)d_in[1];
    const int*   dst = (const int*)d_in[2];
    const int*   seg = (const int*)d_in[3];
    const float* c_eps[2] = {(const float*)d_in[4],  (const float*)d_in[13]};
    const float* c_W1 [2] = {(const float*)d_in[5],  (const float*)d_in[14]};
    const float* c_b1 [2] = {(const float*)d_in[6],  (const float*)d_in[15]};
    const float* c_g1 [2] = {(const float*)d_in[7],  (const float*)d_in[16]};
    const float* c_be1[2] = {(const float*)d_in[8],  (const float*)d_in[17]};
    const float* c_W2 [2] = {(const float*)d_in[9],  (const float*)d_in[18]};
    const float* c_b2 [2] = {(const float*)d_in[10], (const float*)d_in[19]};
    const float* c_g2 [2] = {(const float*)d_in[11], (const float*)d_in[20]};
    const float* c_be2[2] = {(const float*)d_in[12], (const float*)d_in[21]};
    const float* pW[3] = {(const float*)d_in[22], (const float*)d_in[24], (const float*)d_in[26]};
    const float* pb[3] = {(const float*)d_in[23], (const float*)d_in[25], (const float*)d_in[27]};

    float* out_h2 = (float*)d_out;
    float* out_sc = (float*)d_out + (size_t)NN * D;

    float *z, *u, *v, *h1, *sums, *sss, *pool;
    cudaGetSymbolAddress((void**)&z,    g_z);
    cudaGetSymbolAddress((void**)&u,    g_u);
    cudaGetSymbolAddress((void**)&v,    g_v);
    cudaGetSymbolAddress((void**)&h1,   g_h1);
    cudaGetSymbolAddress((void**)&sums, g_sum);
    cudaGetSymbolAddress((void**)&sss,  g_ss);
    cudaGetSymbolAddress((void**)&pool, g_pool);

    const int GEMM_BLOCKS = (NN + 63) / 64;     // 782
    const int ROW_BLOCKS  = (NN + 127) / 128;   // 391
    const int SCAT_BLOCKS = NE / (8 * EPW);     // 18750 (exact)

    k_init<<<1, 1024>>>();
    k_pool0<<<ROW_BLOCKS, 256>>>(h, seg, pool);

    const float* x = h;
    float* youts[2] = {h1, out_h2};
    for (int l = 0; l < 2; l++) {
        k_initz  <<<(NN * D) / 1024, 256>>>(x, c_eps[l]);
        k_scatter<<<SCAT_BLOCKS, 256>>>(x, src, dst);
        float* s1 = sums + (l * 2 + 0) * D; float* q1 = sss + (l * 2 + 0) * D;
        float* s2 = sums + (l * 2 + 1) * D; float* q2 = sss + (l * 2 + 1) * D;
        k_gemm<<<GEMM_BLOCKS, 256>>>(z, c_W1[l], c_b1[l], u,
                                     nullptr, nullptr, nullptr, nullptr,
                                     s1, q1, 0);
        k_gemm<<<GEMM_BLOCKS, 256>>>(u, c_W2[l], c_b2[l], v,
                                     s1, q1, c_g1[l], c_be1[l],
                                     s2, q2, 1);
        k_out<<<ROW_BLOCKS, 256>>>(v, s2, q2, c_g2[l], c_be2[l],
                                   youts[l], pool + (size_t)(l + 1) * NB * D, seg);
        x = h1;
    }
    k_score<<<1, 256>>>(pW[0], pb[0], pW[1], pb[1], pW[2], pb[2], out_sc);
}

// round 5
// speedup vs baseline: 1.7203x; 1.1642x over previous
#include <cuda_runtime.h>
#include <cfloat>

#define NN 50000
#define NE 600000
#define D  128
#define NB 8

// ---------------- scratch (static device memory; no allocs) ----------------
__device__ float g_z [NN * D];
__device__ float g_u [NN * D];
__device__ float g_v [NN * D];
__device__ float g_h1[NN * D];
__device__ float g_sum[4 * D];
__device__ float g_ss [4 * D];
__device__ float g_pool[3 * NB * D];

__device__ __forceinline__ void atomicMaxFloat(float* addr, float v) {
    if (v >= 0.f) atomicMax((int*)addr, __float_as_int(v));
    else          atomicMin((unsigned int*)addr, __float_as_uint(v));
}

__device__ __forceinline__ void cp16(void* smem, const void* g, int srcsize) {
    unsigned s = (unsigned)__cvta_generic_to_shared(smem);
    asm volatile("cp.async.cg.shared.global [%0], [%1], 16, %2;"
                 :: "r"(s), "l"(g), "r"(srcsize));
}
__device__ __forceinline__ unsigned f2tf32(float v) {
    unsigned r;
    asm("cvt.rna.tf32.f32 %0, %1;" : "=r"(r) : "f"(v));
    return r;
}
__device__ __forceinline__ void mma_tf32(float* d, const unsigned* a,
                                         unsigned b0, unsigned b1) {
    asm volatile(
        "mma.sync.aligned.m16n8k8.row.col.f32.tf32.tf32.f32 "
        "{%0,%1,%2,%3}, {%4,%5,%6,%7}, {%8,%9}, {%0,%1,%2,%3};"
        : "+f"(d[0]), "+f"(d[1]), "+f"(d[2]), "+f"(d[3])
        : "r"(a[0]), "r"(a[1]), "r"(a[2]), "r"(a[3]), "r"(b0), "r"(b1));
}

// ---------------- init: zero stats, pool = -FLT_MAX ----------------
__global__ void k_init() {
    int t = threadIdx.x;
    if (t < 4 * D) { g_sum[t] = 0.f; g_ss[t] = 0.f; }
    for (int i = t; i < 3 * NB * D; i += 1024) g_pool[i] = -FLT_MAX;
}

// ---------------- z = (1+eps) * x ----------------
__global__ __launch_bounds__(256) void k_initz(const float* __restrict__ x,
                                               const float* __restrict__ epsp) {
    float s = 1.0f + *epsp;
    size_t i = ((size_t)blockIdx.x * 256 + threadIdx.x) * 4;
    float4 v = *(const float4*)(x + i);
    v.x *= s; v.y *= s; v.z *= s; v.w *= s;
    *(float4*)(g_z + i) = v;
}

// ------- scatter: z[dst] += x[src]; warp per 4 edges, red.global.v4 --------
#define EPW 4
__global__ __launch_bounds__(256) void k_scatter(const float* __restrict__ x,
                                                 const int* __restrict__ src,
                                                 const int* __restrict__ dst) {
    int warp = (blockIdx.x * 256 + threadIdx.x) >> 5;
    int lane = threadIdx.x & 31;
    int e0   = warp * EPW;
    int4 s4 = *(const int4*)(src + e0);
    int4 d4 = *(const int4*)(dst + e0);
    int ss[EPW] = {s4.x, s4.y, s4.z, s4.w};
    int dd[EPW] = {d4.x, d4.y, d4.z, d4.w};
    float4 v[EPW];
#pragma unroll
    for (int i = 0; i < EPW; i++)
        v[i] = *(const float4*)(x + (size_t)ss[i] * D + lane * 4);
#pragma unroll
    for (int i = 0; i < EPW; i++) {
        float* p = g_z + (size_t)dd[i] * D + lane * 4;
        asm volatile("red.global.add.v4.f32 [%0], {%1, %2, %3, %4};"
                     :: "l"(p), "f"(v[i].x), "f"(v[i].y), "f"(v[i].z), "f"(v[i].w)
                     : "memory");
    }
}

// ---------- TF32 tensor-core GEMM: 128 rows x 128 cols per block -----------
// bnrelu=0: out = A @ W + bias
// bnrelu=1: out = relu(bn(A)) @ W + bias
// Both variants accumulate column sum/sumsq of the output into out_sum/out_ss.
#define ASTRIDE 20    // A chunk row stride (floats), bank-conflict-free frags
#define WSTRIDE 136   // W chunk row stride (floats), bank-conflict-free frags
#define NCHUNK  8     // K=128 in chunks of 16
__global__ __launch_bounds__(256) void k_gemm(
    const float* __restrict__ A, const float* __restrict__ W,
    const float* __restrict__ bias, float* __restrict__ out,
    const float* __restrict__ in_sum, const float* __restrict__ in_ss,
    const float* __restrict__ gamma, const float* __restrict__ beta,
    float* __restrict__ out_sum, float* __restrict__ out_ss,
    int bnrelu)
{
    __shared__ float As[2][128 * ASTRIDE];
    __shared__ float Wt[2][16 * WSTRIDE];
    __shared__ float sc_s[128], sh_s[128];

    const int tid  = threadIdx.x;
    const int wid  = tid >> 5;
    const int lane = tid & 31;
    const int gid  = lane >> 2;   // 0..7
    const int qid  = lane & 3;    // 0..3
    const int wm   = (wid >> 1) * 32;  // warp row offset 0..96
    const int wn   = (wid & 1) * 64;   // warp col offset 0/64
    const int row0 = blockIdx.x * 128;

    if (bnrelu && tid < 128) {
        float m   = in_sum[tid] * (1.0f / NN);
        float var = in_ss[tid] * (1.0f / NN) - m * m;
        float rs  = rsqrtf(var + 1e-5f);
        float sc  = gamma[tid] * rs;
        sc_s[tid] = sc;
        sh_s[tid] = fmaf(-m, sc, beta[tid]);
    }

    float acc[2][8][4];
#pragma unroll
    for (int mt = 0; mt < 2; mt++)
#pragma unroll
        for (int nt = 0; nt < 8; nt++)
#pragma unroll
            for (int j = 0; j < 4; j++) acc[mt][nt][j] = 0.f;

    // ---- async chunk loader ----
    const int a_r  = tid >> 2;          // 0..63 (+64)
    const int a_c4 = (tid & 3) * 4;
    const int w_r  = tid >> 5;          // 0..7 (+8)
    const int w_c4 = (tid & 31) * 4;

#define LOAD_CHUNK(c, b)                                                       \
    {                                                                          \
        _Pragma("unroll")                                                      \
        for (int p = 0; p < 2; p++) {                                          \
            int r = a_r + p * 64;                                              \
            int gr = row0 + r;                                                 \
            const float* gp = A + (size_t)(gr < NN ? gr : 0) * D + (c)*16 + a_c4; \
            cp16(&As[b][r * ASTRIDE + a_c4], gp, gr < NN ? 16 : 0);            \
        }                                                                      \
        _Pragma("unroll")                                                      \
        for (int p = 0; p < 2; p++) {                                          \
            int r = w_r + p * 8;                                               \
            cp16(&Wt[b][r * WSTRIDE + w_c4], W + (size_t)((c)*16 + r) * D + w_c4, 16); \
        }                                                                      \
        asm volatile("cp.async.commit_group;");                                \
    }

    LOAD_CHUNK(0, 0);

    for (int c = 0; c < NCHUNK; c++) {
        if (c + 1 < NCHUNK) {
            int nb = (c + 1) & 1;
            LOAD_CHUNK(c + 1, nb);
            asm volatile("cp.async.wait_group 1;");
        } else {
            asm volatile("cp.async.wait_group 0;");
        }
        __syncthreads();
        const int b = c & 1;
#pragma unroll
        for (int k8 = 0; k8 < 2; k8++) {
            const int k0 = k8 * 8;
            const int cA = k0 + qid;
            unsigned afr[2][4];
            float sc0 = 1.f, sh0 = 0.f, sc1 = 1.f, sh1 = 0.f;
            if (bnrelu) {
                int kg = c * 16 + cA;
                sc0 = sc_s[kg];     sh0 = sh_s[kg];
                sc1 = sc_s[kg + 4]; sh1 = sh_s[kg + 4];
            }
#pragma unroll
            for (int mt = 0; mt < 2; mt++) {
                int r = wm + 16 * mt + gid;
                float f0 = As[b][r * ASTRIDE + cA];
                float f1 = As[b][(r + 8) * ASTRIDE + cA];
                float f2 = As[b][r * ASTRIDE + cA + 4];
                float f3 = As[b][(r + 8) * ASTRIDE + cA + 4];
                if (bnrelu) {
                    f0 = fmaxf(fmaf(f0, sc0, sh0), 0.f);
                    f1 = fmaxf(fmaf(f1, sc0, sh0), 0.f);
                    f2 = fmaxf(fmaf(f2, sc1, sh1), 0.f);
                    f3 = fmaxf(fmaf(f3, sc1, sh1), 0.f);
                }
                afr[mt][0] = f2tf32(f0);
                afr[mt][1] = f2tf32(f1);
                afr[mt][2] = f2tf32(f2);
                afr[mt][3] = f2tf32(f3);
            }
#pragma unroll
            for (int nt = 0; nt < 8; nt++) {
                int cB = wn + nt * 8 + gid;
                unsigned b0 = f2tf32(Wt[b][(k0 + qid) * WSTRIDE + cB]);
                unsigned b1 = f2tf32(Wt[b][(k0 + qid + 4) * WSTRIDE + cB]);
                mma_tf32(acc[0][nt], afr[0], b0, b1);
                mma_tf32(acc[1][nt], afr[1], b0, b1);
            }
        }
        __syncthreads();
    }

    // ---- epilogue: bias, store, column stats ----
#pragma unroll
    for (int nt = 0; nt < 8; nt++) {
        int col = wn + nt * 8 + 2 * qid;
        float2 bb = *(const float2*)(bias + col);
        float s0 = 0.f, s1 = 0.f, q0 = 0.f, q1 = 0.f;
#pragma unroll
        for (int mt = 0; mt < 2; mt++) {
            int r = row0 + wm + 16 * mt + gid;
            float v0 = acc[mt][nt][0] + bb.x;
            float v1 = acc[mt][nt][1] + bb.y;
            float v2 = acc[mt][nt][2] + bb.x;
            float v3 = acc[mt][nt][3] + bb.y;
            if (r < NN) {
                *(float2*)(out + (size_t)r * D + col) = make_float2(v0, v1);
                s0 += v0; s1 += v1; q0 += v0 * v0; q1 += v1 * v1;
            }
            if (r + 8 < NN) {
                *(float2*)(out + (size_t)(r + 8) * D + col) = make_float2(v2, v3);
                s0 += v2; s1 += v3; q0 += v2 * v2; q1 += v3 * v3;
            }
        }
#pragma unroll
        for (int m = 4; m < 32; m <<= 1) {
            s0 += __shfl_xor_sync(0xffffffffu, s0, m);
            s1 += __shfl_xor_sync(0xffffffffu, s1, m);
            q0 += __shfl_xor_sync(0xffffffffu, q0, m);
            q1 += __shfl_xor_sync(0xffffffffu, q1, m);
        }
        if (lane < 4) {
            atomicAdd(&out_sum[col], s0);
            atomicAdd(&out_sum[col + 1], s1);
            atomicAdd(&out_ss[col], q0);
            atomicAdd(&out_ss[col + 1], q1);
        }
    }
}

// -------- y = leaky_relu(bn(v)); write y; segment-max pooling --------------
__global__ __launch_bounds__(256) void k_out(
    const float* __restrict__ v, const float* __restrict__ in_sum,
    const float* __restrict__ in_ss, const float* __restrict__ gamma,
    const float* __restrict__ beta, float* __restrict__ y,
    float* __restrict__ pool, const int* __restrict__ seg)
{
    __shared__ float sc_s[128], sh_s[128];
    __shared__ int seg_s[128];
    int tid  = threadIdx.x;
    int row0 = blockIdx.x * 128;
    if (tid < 128) {
        float m   = in_sum[tid] * (1.0f / NN);
        float var = in_ss[tid] * (1.0f / NN) - m * m;
        float rs  = rsqrtf(var + 1e-5f);
        float sc  = gamma[tid] * rs;
        sc_s[tid] = sc;
        sh_s[tid] = fmaf(-m, sc, beta[tid]);
        int r = row0 + tid;
        seg_s[tid] = (r < NN) ? seg[r] : -1;
    }
    __syncthreads();
    int c    = tid & 127;
    int rbeg = (tid >> 7) * 64;
    float sc = sc_s[c], sh = sh_s[c];
    float runmax = -FLT_MAX;
    int cur = -1;
    for (int i = 0; i < 64; i++) {
        int r = rbeg + i, gr = row0 + r;
        if (gr >= NN) break;
        float val = fmaf(v[(size_t)gr * D + c], sc, sh);
        val = (val > 0.f) ? val : val * 0.01f;
        y[(size_t)gr * D + c] = val;
        int s = seg_s[r];
        if (s != cur) {
            if (cur >= 0) atomicMaxFloat(&pool[cur * D + c], runmax);
            cur = s; runmax = val;
        } else runmax = fmaxf(runmax, val);
    }
    if (cur >= 0) atomicMaxFloat(&pool[cur * D + c], runmax);
}

// -------- segment-max pooling of raw input h --------------
__global__ __launch_bounds__(256) void k_pool0(const float* __restrict__ x,
                                               const int* __restrict__ seg,
                                               float* __restrict__ pool)
{
    __shared__ int seg_s[128];
    int tid  = threadIdx.x;
    int row0 = blockIdx.x * 128;
    if (tid < 128) { int r = row0 + tid; seg_s[tid] = (r < NN) ? seg[r] : -1; }
    __syncthreads();
    int c    = tid & 127;
    int rbeg = (tid >> 7) * 64;
    float runmax = -FLT_MAX;
    int cur = -1;
    for (int i = 0; i < 64; i++) {
        int r = rbeg + i, gr = row0 + r;
        if (gr >= NN) break;
        float val = x[(size_t)gr * D + c];
        int s = seg_s[r];
        if (s != cur) {
            if (cur >= 0) atomicMaxFloat(&pool[cur * D + c], runmax);
            cur = s; runmax = val;
        } else runmax = fmaxf(runmax, val);
    }
    if (cur >= 0) atomicMaxFloat(&pool[cur * D + c], runmax);
}

// -------- score = sum_l pooled_l @ pW_l + pb_l  (8x128, one block) ---------
__global__ __launch_bounds__(256) void k_score(
    const float* __restrict__ W0, const float* __restrict__ b0,
    const float* __restrict__ W1, const float* __restrict__ b1,
    const float* __restrict__ W2, const float* __restrict__ b2,
    float* __restrict__ out)
{
    __shared__ float ps[3 * NB * D];
    int tid = threadIdx.x;
    for (int i = tid; i < 3 * NB * D; i += 256) ps[i] = g_pool[i];
    __syncthreads();
    int b  = tid >> 5;
    int j0 = (tid & 31) * 4;
    float acc[4];
#pragma unroll
    for (int j = 0; j < 4; j++) acc[j] = b0[j0 + j] + b1[j0 + j] + b2[j0 + j];
    const float* Ws[3] = {W0, W1, W2};
    for (int l = 0; l < 3; l++) {
        const float* pl = ps + (l * NB + b) * D;
        const float* Wl = Ws[l];
        for (int k = 0; k < D; k++) {
            float p = pl[k];
            float4 w = *(const float4*)(Wl + (size_t)k * D + j0);
            acc[0] = fmaf(p, w.x, acc[0]);
            acc[1] = fmaf(p, w.y, acc[1]);
            acc[2] = fmaf(p, w.z, acc[2]);
            acc[3] = fmaf(p, w.w, acc[3]);
        }
    }
#pragma unroll
    for (int j = 0; j < 4; j++) out[b * D + j0 + j] = acc[j];
}

// ---------------------------------------------------------------------------
extern "C" void kernel_launch(void* const* d_in, const int* in_sizes, int n_in,
                              void* d_out, int out_size)
{
    const float* h   = (const float*)d_in[0];
    const int*   src = (const int*)d_in[1];
    const int*   dst = (const int*)d_in[2];
    const int*   seg = (const int*)d_in[3];
    const float* c_eps[2] = {(const float*)d_in[4],  (const float*)d_in[13]};
    const float* c_W1 [2] = {(const float*)d_in[5],  (const float*)d_in[14]};
    const float* c_b1 [2] = {(const float*)d_in[6],  (const float*)d_in[15]};
    const float* c_g1 [2] = {(const float*)d_in[7],  (const float*)d_in[16]};
    const float* c_be1[2] = {(const float*)d_in[8],  (const float*)d_in[17]};
    const float* c_W2 [2] = {(const float*)d_in[9],  (const float*)d_in[18]};
    const float* c_b2 [2] = {(const float*)d_in[10], (const float*)d_in[19]};
    const float* c_g2 [2] = {(const float*)d_in[11], (const float*)d_in[20]};
    const float* c_be2[2] = {(const float*)d_in[12], (const float*)d_in[21]};
    const float* pW[3] = {(const float*)d_in[22], (const float*)d_in[24], (const float*)d_in[26]};
    const float* pb[3] = {(const float*)d_in[23], (const float*)d_in[25], (const float*)d_in[27]};

    float* out_h2 = (float*)d_out;
    float* out_sc = (float*)d_out + (size_t)NN * D;

    float *z, *u, *v, *h1, *sums, *sss, *pool;
    cudaGetSymbolAddress((void**)&z,    g_z);
    cudaGetSymbolAddress((void**)&u,    g_u);
    cudaGetSymbolAddress((void**)&v,    g_v);
    cudaGetSymbolAddress((void**)&h1,   g_h1);
    cudaGetSymbolAddress((void**)&sums, g_sum);
    cudaGetSymbolAddress((void**)&sss,  g_ss);
    cudaGetSymbolAddress((void**)&pool, g_pool);

    const int GEMM_BLOCKS = (NN + 127) / 128;   // 391
    const int ROW_BLOCKS  = (NN + 127) / 128;   // 391
    const int SCAT_BLOCKS = NE / (8 * EPW);     // 18750

    k_init<<<1, 1024>>>();
    k_pool0<<<ROW_BLOCKS, 256>>>(h, seg, pool);

    const float* x = h;
    float* youts[2] = {h1, out_h2};
    for (int l = 0; l < 2; l++) {
        k_initz  <<<(NN * D) / 1024, 256>>>(x, c_eps[l]);
        k_scatter<<<SCAT_BLOCKS, 256>>>(x, src, dst);
        float* s1 = sums + (l * 2 + 0) * D; float* q1 = sss + (l * 2 + 0) * D;
        float* s2 = sums + (l * 2 + 1) * D; float* q2 = sss + (l * 2 + 1) * D;
        k_gemm<<<GEMM_BLOCKS, 256>>>(z, c_W1[l], c_b1[l], u,
                                     nullptr, nullptr, nullptr, nullptr,
                                     s1, q1, 0);
        k_gemm<<<GEMM_BLOCKS, 256>>>(u, c_W2[l], c_b2[l], v,
                                     s1, q1, c_g1[l], c_be1[l],
                                     s2, q2, 1);
        k_out<<<ROW_BLOCKS, 256>>>(v, s2, q2, c_g2[l], c_be2[l],
                                   youts[l], pool + (size_t)(l + 1) * NB * D, seg);
        x = h1;
    }
    k_score<<<1, 256>>>(pW[0], pb[0], pW[1], pb[1], pW[2], pb[2], out_sc);
}